// round 16
// baseline (speedup 1.0000x reference)
#include <cuda_runtime.h>
#include <cuda_bf16.h>

#define BB 4
#define TT 16
#define HH 64
#define WW 64
#define CC 32
#define FF 64
#define OC 256   // 4*F

typedef unsigned int u32;

// ---------------- scratch (device globals; no allocations allowed) ----------
__device__ __nv_bfloat16 g_xh[(size_t)BB*TT*HH*WW*CC];   // LN output hi
__device__ __nv_bfloat16 g_xl[(size_t)BB*TT*HH*WW*CC];   // LN output lo
__device__ float         g_zx[(size_t)BB*TT*HH*WW*OC];   // input-conv result
__device__ __nv_bfloat16 g_hh[(size_t)BB*HH*WW*FF];      // h hi
__device__ __nv_bfloat16 g_hl[(size_t)BB*HH*WW*FF];      // h lo
__device__ float         g_c [(size_t)BB*HH*WW*FF];
__device__ float         g_z [(size_t)BB*HH*WW*OC];      // recurrent conv result
// packed bf16 hi/lo weights in smem row layout: [(chunk*8+ocb)][kp*32+oc][72 bf16]
__device__ __nv_bfloat16 g_wx[(size_t)1*8*288*72];       // convx: 1 ic chunk
__device__ __nv_bfloat16 g_wh[(size_t)2*8*288*72];       // convh: 2 ic chunks

// ---------------- bf16 mma (m16n8k16, fp32 accum) ---------------------------
#define MMA_BF16(d, a0,a1,a2,a3, b0,b1)                                        \
    asm volatile("mma.sync.aligned.m16n8k16.row.col.f32.bf16.bf16.f32 "        \
        "{%0,%1,%2,%3}, {%4,%5,%6,%7}, {%8,%9}, {%0,%1,%2,%3};"                \
        : "+f"((d)[0]), "+f"((d)[1]), "+f"((d)[2]), "+f"((d)[3])               \
        : "r"(a0), "r"(a1), "r"(a2), "r"(a3), "r"(b0), "r"(b1))

// fast tanh: (e^{2x}-1)/(e^{2x}+1), MUFU-based, rel err ~1e-6
__device__ __forceinline__ float ftanh(float x) {
    float xc = fminf(fmaxf(x, -15.f), 15.f);
    float e = __expf(2.f * xc);
    return __fdividef(e - 1.f, e + 1.f);
}

// ---------------- weight pack: fp32 [9][IC][OC] -> bf16 hi/lo rows ----------
__global__ void packw_kernel(const float* __restrict__ W,
                             __nv_bfloat16* __restrict__ dst, int IC) {
    int i = blockIdx.x * 256 + threadIdx.x;
    int total = (IC >> 5) * 8 * 9 * 32 * 32;
    if (i >= total) return;
    int icl = i & 31; int r = i >> 5;
    int oc  = r & 31; r >>= 5;
    int kp  = r % 9;  r /= 9;
    int ocb = r & 7;  int chunk = r >> 3;
    float v = W[((size_t)kp * IC + chunk * 32 + icl) * OC + ocb * 32 + oc];
    __nv_bfloat16 h = __float2bfloat16(v);
    __nv_bfloat16 l = __float2bfloat16(v - __bfloat162float(h));
    __nv_bfloat16* br = dst + ((size_t)(chunk * 8 + ocb) * 288 + kp * 32 + oc) * 72;
    br[icl] = h; br[32 + icl] = l;
}

// ---------------- LayerNorm over channel axis -> bf16 hi/lo -----------------
__global__ void ln_kernel(const float* __restrict__ x,
                          const float* __restrict__ gamma,
                          const float* __restrict__ beta) {
    int row  = blockIdx.x * 8 + (threadIdx.x >> 5);
    int lane = threadIdx.x & 31;
    float v = x[(size_t)row * CC + lane];
    float s = v, s2 = v * v;
    #pragma unroll
    for (int o = 16; o; o >>= 1) {
        s  += __shfl_xor_sync(0xffffffffu, s,  o);
        s2 += __shfl_xor_sync(0xffffffffu, s2, o);
    }
    float mu  = s * (1.f / 32.f);
    float var = s2 * (1.f / 32.f) - mu * mu;
    float inv = rsqrtf(var + 1e-3f);
    float xn = (v - mu) * inv * gamma[lane] + beta[lane];
    __nv_bfloat16 hi = __float2bfloat16(xn);
    size_t idx = (size_t)row * CC + lane;
    g_xh[idx] = hi;
    g_xl[idx] = __float2bfloat16(xn - __bfloat162float(hi));
}

// A halo staging (shared by both convs): 18x18 tile, bf16 hi|lo per 144B row
#define STAGE_A(Ah, Al, IC, ch0)                                               \
    for (int i = tid; i < 324 * 8; i += 256) {                                 \
        int sp = i >> 3, r = i & 7;                                            \
        int ry = sp / 18, rx = sp - ry * 18;                                   \
        int gy = ty0 - 1 + ry, gx = tx0 - 1 + rx;                              \
        uint4 v = make_uint4(0u, 0u, 0u, 0u);                                  \
        if (gy >= 0 && gy < HH && gx >= 0 && gx < WW) {                        \
            const __nv_bfloat16* src = (r < 4 ? (Ah) : (Al))                   \
                + ((size_t)gy * WW + gx) * (IC) + (ch0) + ((r & 3) << 3);      \
            v = *(const uint4*)src;                                            \
        }                                                                      \
        *(uint4*)(s_a + sp * 144 + ((r & 3) << 4) + ((r < 4) ? 0 : 64)) = v;   \
    }

// ---------------- input conv: zx = conv3x3(xn, Wx) + b ----------------------
// grid (2, 16, 64): block stages A ONCE, loops 4 oc-groups (B restaged each).
__global__ __launch_bounds__(256, 2) void convx_mma(
    const __nv_bfloat16* __restrict__ Ahi, const __nv_bfloat16* __restrict__ Alo,
    const __nv_bfloat16* __restrict__ Wp,
    const float* __restrict__ bias, float* __restrict__ zout)
{
    extern __shared__ __align__(16) unsigned char smraw[];
    char* s_a = (char*)smraw;            // 324*144 = 46656 B
    char* s_b = (char*)smraw + 46656;    // 288*144 = 41472 B

    int ocq = blockIdx.x, tile = blockIdx.y, img = blockIdx.z;
    int tid = threadIdx.x;
    int ty0 = (tile >> 2) * 16, tx0 = (tile & 3) * 16;
    int w = tid >> 5, lane = tid & 31, gid = lane >> 2, tig = lane & 3;

    const __nv_bfloat16* Ah = Ahi + (size_t)img * HH * WW * CC;
    const __nv_bfloat16* Al = Alo + (size_t)img * HH * WW * CC;
    STAGE_A(Ah, Al, CC, 0)

    float* zo = zout + (size_t)img * HH * WW * OC;

    #pragma unroll 1
    for (int ocp = 0; ocp < 4; ocp++) {
        int ocb = ocq * 4 + ocp, oc0 = ocb * 32;
        {
            const uint4* wsrc = (const uint4*)(Wp + (size_t)ocb * 288 * 72);
            uint4* wdst = (uint4*)s_b;
            for (int i = tid; i < 2592; i += 256) wdst[i] = wsrc[i];
        }
        __syncthreads();

        float acc[2][4][4];
        #pragma unroll
        for (int n = 0; n < 4; n++) {
            float b0 = bias[oc0 + n * 8 + tig * 2];
            float b1 = bias[oc0 + n * 8 + tig * 2 + 1];
            #pragma unroll
            for (int t = 0; t < 2; t++) {
                acc[t][n][0] = b0; acc[t][n][1] = b1;
                acc[t][n][2] = b0; acc[t][n][3] = b1;
            }
        }

        #pragma unroll 1
        for (int kp = 0; kp < 9; kp++) {
            int ky = (kp >= 6) ? 2 : ((kp >= 3) ? 1 : 0);
            int kx = kp - ky * 3;
            #pragma unroll
            for (int s = 0; s < 2; s++) {
                u32 bh[4][2], bl[4][2];
                #pragma unroll
                for (int n = 0; n < 4; n++) {
                    const char* bp = s_b + (kp * 32 + n * 8 + gid) * 144 + s * 32 + tig * 4;
                    bh[n][0] = *(const u32*)bp;        bh[n][1] = *(const u32*)(bp + 16);
                    bl[n][0] = *(const u32*)(bp + 64); bl[n][1] = *(const u32*)(bp + 80);
                }
                #pragma unroll
                for (int t = 0; t < 2; t++) {
                    const char* ap = s_a + ((w + 8 * t + ky) * 18 + gid + kx) * 144
                                   + s * 32 + tig * 4;
                    u32 ah0 = *(const u32*)ap;
                    u32 ah2 = *(const u32*)(ap + 16);
                    u32 ah1 = *(const u32*)(ap + 8 * 144);
                    u32 ah3 = *(const u32*)(ap + 8 * 144 + 16);
                    u32 al0 = *(const u32*)(ap + 64);
                    u32 al2 = *(const u32*)(ap + 80);
                    u32 al1 = *(const u32*)(ap + 8 * 144 + 64);
                    u32 al3 = *(const u32*)(ap + 8 * 144 + 80);
                    #pragma unroll
                    for (int n = 0; n < 4; n++) {
                        MMA_BF16(acc[t][n], ah0, ah1, ah2, ah3, bh[n][0], bh[n][1]);
                        MMA_BF16(acc[t][n], ah0, ah1, ah2, ah3, bl[n][0], bl[n][1]);
                        MMA_BF16(acc[t][n], al0, al1, al2, al3, bh[n][0], bh[n][1]);
                    }
                }
            }
        }

        #pragma unroll
        for (int t = 0; t < 2; t++) {
            int y = ty0 + w + t * 8;
            float* r1 = zo + ((size_t)y * WW + tx0 + gid) * OC + oc0 + tig * 2;
            #pragma unroll
            for (int n = 0; n < 4; n++) {
                *(float2*)(r1 + n * 8)          = make_float2(acc[t][n][0], acc[t][n][1]);
                *(float2*)(r1 + 8 * OC + n * 8) = make_float2(acc[t][n][2], acc[t][n][3]);
            }
        }
        __syncthreads();
    }
}

// ---------------- recurrent conv: z = zx[:,t] + conv3x3(h, Wh) --------------
// grid (4, 16, 4): block holds 2 oc-groups in registers (64 accs), stages the
// A chunk once per ic-chunk (was once per oc-block).
__global__ __launch_bounds__(256, 2) void convh_mma(
    const __nv_bfloat16* __restrict__ Ahi, const __nv_bfloat16* __restrict__ Alo,
    const __nv_bfloat16* __restrict__ Wp,
    const float* __restrict__ zseed, float* __restrict__ zout, int t_step)
{
    extern __shared__ __align__(16) unsigned char smraw[];
    char* s_a = (char*)smraw;            // 46656 B
    char* s_b = (char*)smraw + 46656;    // 41472 B

    int ocq = blockIdx.x, tile = blockIdx.y, img = blockIdx.z;
    int tid = threadIdx.x;
    int ty0 = (tile >> 2) * 16, tx0 = (tile & 3) * 16;
    int w = tid >> 5, lane = tid & 31, gid = lane >> 2, tig = lane & 3;

    float acc[2][2][4][4];               // [ocp][t][n][frag]
    {
        const float* zs = zseed + ((size_t)(img * TT + t_step) * HH * WW) * OC;
        #pragma unroll
        for (int ocp = 0; ocp < 2; ocp++) {
            int oc0 = (ocq * 2 + ocp) * 32;
            #pragma unroll
            for (int t = 0; t < 2; t++) {
                int y = ty0 + w + t * 8;
                const float* r1 = zs + ((size_t)y * WW + tx0 + gid) * OC + oc0 + tig * 2;
                #pragma unroll
                for (int n = 0; n < 4; n++) {
                    float2 v1 = *(const float2*)(r1 + n * 8);
                    float2 v2 = *(const float2*)(r1 + 8 * OC + n * 8);
                    acc[ocp][t][n][0] = v1.x; acc[ocp][t][n][1] = v1.y;
                    acc[ocp][t][n][2] = v2.x; acc[ocp][t][n][3] = v2.y;
                }
            }
        }
    }

    const __nv_bfloat16* Ah = Ahi + (size_t)img * HH * WW * FF;
    const __nv_bfloat16* Al = Alo + (size_t)img * HH * WW * FF;

    #pragma unroll 1
    for (int chunk = 0; chunk < 2; chunk++) {
        STAGE_A(Ah, Al, FF, chunk * 32)
        #pragma unroll 1
        for (int ocp = 0; ocp < 2; ocp++) {
            {
                const uint4* wsrc = (const uint4*)(Wp
                    + (size_t)(chunk * 8 + ocq * 2 + ocp) * 288 * 72);
                uint4* wdst = (uint4*)s_b;
                for (int i = tid; i < 2592; i += 256) wdst[i] = wsrc[i];
            }
            __syncthreads();

            #pragma unroll 1
            for (int kp = 0; kp < 9; kp++) {
                int ky = (kp >= 6) ? 2 : ((kp >= 3) ? 1 : 0);
                int kx = kp - ky * 3;
                #pragma unroll
                for (int s = 0; s < 2; s++) {
                    u32 bh[4][2], bl[4][2];
                    #pragma unroll
                    for (int n = 0; n < 4; n++) {
                        const char* bp = s_b + (kp * 32 + n * 8 + gid) * 144 + s * 32 + tig * 4;
                        bh[n][0] = *(const u32*)bp;        bh[n][1] = *(const u32*)(bp + 16);
                        bl[n][0] = *(const u32*)(bp + 64); bl[n][1] = *(const u32*)(bp + 80);
                    }
                    #pragma unroll
                    for (int t = 0; t < 2; t++) {
                        const char* ap = s_a + ((w + 8 * t + ky) * 18 + gid + kx) * 144
                                       + s * 32 + tig * 4;
                        u32 ah0 = *(const u32*)ap;
                        u32 ah2 = *(const u32*)(ap + 16);
                        u32 ah1 = *(const u32*)(ap + 8 * 144);
                        u32 ah3 = *(const u32*)(ap + 8 * 144 + 16);
                        u32 al0 = *(const u32*)(ap + 64);
                        u32 al2 = *(const u32*)(ap + 80);
                        u32 al1 = *(const u32*)(ap + 8 * 144 + 64);
                        u32 al3 = *(const u32*)(ap + 8 * 144 + 80);
                        #pragma unroll
                        for (int n = 0; n < 4; n++) {
                            MMA_BF16(acc[ocp][t][n], ah0, ah1, ah2, ah3, bh[n][0], bh[n][1]);
                            MMA_BF16(acc[ocp][t][n], ah0, ah1, ah2, ah3, bl[n][0], bl[n][1]);
                            MMA_BF16(acc[ocp][t][n], al0, al1, al2, al3, bh[n][0], bh[n][1]);
                        }
                    }
                }
            }
            __syncthreads();
        }
    }

    float* zo = zout + (size_t)img * HH * WW * OC;
    #pragma unroll
    for (int ocp = 0; ocp < 2; ocp++) {
        int oc0 = (ocq * 2 + ocp) * 32;
        #pragma unroll
        for (int t = 0; t < 2; t++) {
            int y = ty0 + w + t * 8;
            float* r1 = zo + ((size_t)y * WW + tx0 + gid) * OC + oc0 + tig * 2;
            #pragma unroll
            for (int n = 0; n < 4; n++) {
                *(float2*)(r1 + n * 8)          = make_float2(acc[ocp][t][n][0], acc[ocp][t][n][1]);
                *(float2*)(r1 + 8 * OC + n * 8) = make_float2(acc[ocp][t][n][2], acc[ocp][t][n][3]);
            }
        }
    }
}

// ---------------- LSTM gates + MaxPool(2x2) fused ---------------------------
// FIRST=true: t=0 path — z comes straight from g_zx (conv(h0)=0), c_prev=0,
// so this kernel also fully initializes g_c / g_hh / g_hl (no zero kernel).
template<bool FIRST>
__global__ void gatepool_kernel(const float* __restrict__ zsrc, size_t bstride,
                                float* __restrict__ out, int t) {
    int i = blockIdx.x * blockDim.x + threadIdx.x;   // B*32*32*F = 262144
    if (i >= BB * 32 * 32 * FF) return;
    int f = i & 63;
    int r = i >> 6;
    int xo = r & 31; r >>= 5;
    int yo = r & 31;
    int b  = r >> 5;

    const float* zb = zsrc + (size_t)b * bstride;
    float m = -1e30f;
    #pragma unroll
    for (int dy = 0; dy < 2; dy++) {
        #pragma unroll
        for (int dx = 0; dx < 2; dx++) {
            int y = yo * 2 + dy, x = xo * 2 + dx;
            const float* z = zb + ((size_t)y * WW + x) * OC;
            float zi = z[f], zf = z[64 + f], zc = z[128 + f], zo_ = z[192 + f];
            float ig = __saturatef(0.2f * zi + 0.5f);
            float og = __saturatef(0.2f * zo_ + 0.5f);
            size_t hi = (((size_t)b * HH + y) * WW + x) * FF + f;
            float c;
            if (FIRST) {
                c = ig * ftanh(zc);
            } else {
                float fg = __saturatef(0.2f * zf + 0.5f);
                c = fg * g_c[hi] + ig * ftanh(zc);
            }
            g_c[hi] = c;
            float h = og * ftanh(c);
            __nv_bfloat16 hh = __float2bfloat16(h);
            g_hh[hi] = hh;
            g_hl[hi] = __float2bfloat16(h - __bfloat162float(hh));
            m = fmaxf(m, h);
        }
    }
    out[(((((size_t)b * TT) + t) * 32 + yo) * 32 + xo) * FF + f] = m;
}

// ---------------- launch ----------------------------------------------------
extern "C" void kernel_launch(void* const* d_in, const int* in_sizes, int n_in,
                              void* d_out, int out_size) {
    const float* x     = (const float*)d_in[0];
    const float* gamma = (const float*)d_in[1];
    const float* beta  = (const float*)d_in[2];
    const float* Wx    = (const float*)d_in[3];
    const float* Wh    = (const float*)d_in[4];
    const float* bias  = (const float*)d_in[5];
    float* out = (float*)d_out;

    const int SMEM = 46656 + 41472;   // 88128 B -> 2 CTAs/SM
    cudaFuncSetAttribute(convx_mma, cudaFuncAttributeMaxDynamicSharedMemorySize, SMEM);
    cudaFuncSetAttribute(convh_mma, cudaFuncAttributeMaxDynamicSharedMemorySize, SMEM);

    __nv_bfloat16 *d_xh, *d_xl, *d_hh, *d_hl, *d_wx, *d_wh;
    float *d_zx, *d_z;
    cudaGetSymbolAddress((void**)&d_xh, g_xh);
    cudaGetSymbolAddress((void**)&d_xl, g_xl);
    cudaGetSymbolAddress((void**)&d_hh, g_hh);
    cudaGetSymbolAddress((void**)&d_hl, g_hl);
    cudaGetSymbolAddress((void**)&d_wx, g_wx);
    cudaGetSymbolAddress((void**)&d_wh, g_wh);
    cudaGetSymbolAddress((void**)&d_zx, g_zx);
    cudaGetSymbolAddress((void**)&d_z,  g_z);

    const int GP_GRID = (BB * 32 * 32 * FF + 255) / 256;

    // pack weights to bf16 hi/lo smem-image layout (every call: deterministic)
    packw_kernel<<<(1*8*9*32*32 + 255) / 256, 256>>>(Wx, d_wx, CC);
    packw_kernel<<<(2*8*9*32*32 + 255) / 256, 256>>>(Wh, d_wh, FF);

    // LayerNorm -> bf16 hi/lo
    ln_kernel<<<(BB * TT * HH * WW) / 8, 256>>>(x, gamma, beta);

    // input conv over all timesteps at once (tensor pipe)
    convx_mma<<<dim3(2, 16, BB * TT), 256, SMEM>>>(d_xh, d_xl, d_wx, bias, d_zx);

    // t = 0: h==0 -> z == zx; gates read g_zx directly, init c/h
    gatepool_kernel<true><<<GP_GRID, 256>>>(
        d_zx, (size_t)TT * HH * WW * OC, out, 0);

    // recurrent loop
    for (int t = 1; t < TT; t++) {
        convh_mma<<<dim3(4, 16, BB), 256, SMEM>>>(d_hh, d_hl, d_wh, d_zx, d_z, t);
        gatepool_kernel<false><<<GP_GRID, 256>>>(
            d_z, (size_t)HH * WW * OC, out, t);
    }
}

// round 17
// speedup vs baseline: 1.3477x; 1.3477x over previous
#include <cuda_runtime.h>
#include <cuda_bf16.h>

#define BB 4
#define TT 16
#define HH 64
#define WW 64
#define CC 32
#define FF 64
#define OC 256   // 4*F

typedef unsigned int u32;

// ---------------- scratch (device globals; no allocations allowed) ----------
__device__ __nv_bfloat16 g_xh[(size_t)BB*TT*HH*WW*CC];   // LN output hi
__device__ __nv_bfloat16 g_xl[(size_t)BB*TT*HH*WW*CC];   // LN output lo
__device__ float         g_zx[(size_t)BB*TT*HH*WW*OC];   // input-conv result
__device__ __nv_bfloat16 g_hh[(size_t)BB*HH*WW*FF];      // h hi
__device__ __nv_bfloat16 g_hl[(size_t)BB*HH*WW*FF];      // h lo
__device__ float         g_c [(size_t)BB*HH*WW*FF];
__device__ float         g_z [(size_t)BB*HH*WW*OC];      // recurrent conv result
// packed bf16 hi/lo weights in smem row layout: [(chunk*8+ocb)][kp*32+oc][72 bf16]
__device__ __nv_bfloat16 g_wx[(size_t)1*8*288*72];       // convx: 1 ic chunk
__device__ __nv_bfloat16 g_wh[(size_t)2*8*288*72];       // convh: 2 ic chunks

// ---------------- bf16 mma (m16n8k16, fp32 accum) ---------------------------
#define MMA_BF16(d, a0,a1,a2,a3, b0,b1)                                        \
    asm volatile("mma.sync.aligned.m16n8k16.row.col.f32.bf16.bf16.f32 "        \
        "{%0,%1,%2,%3}, {%4,%5,%6,%7}, {%8,%9}, {%0,%1,%2,%3};"                \
        : "+f"((d)[0]), "+f"((d)[1]), "+f"((d)[2]), "+f"((d)[3])               \
        : "r"(a0), "r"(a1), "r"(a2), "r"(a3), "r"(b0), "r"(b1))

// fast tanh: (e^{2x}-1)/(e^{2x}+1), MUFU-based, rel err ~1e-6
__device__ __forceinline__ float ftanh(float x) {
    float xc = fminf(fmaxf(x, -15.f), 15.f);
    float e = __expf(2.f * xc);
    return __fdividef(e - 1.f, e + 1.f);
}

// ---------------- weight pack: fp32 [9][IC][OC] -> bf16 hi/lo rows ----------
__global__ void packw_kernel(const float* __restrict__ W,
                             __nv_bfloat16* __restrict__ dst, int IC) {
    int i = blockIdx.x * 256 + threadIdx.x;
    int total = (IC >> 5) * 8 * 9 * 32 * 32;
    if (i >= total) return;
    int icl = i & 31; int r = i >> 5;
    int oc  = r & 31; r >>= 5;
    int kp  = r % 9;  r /= 9;
    int ocb = r & 7;  int chunk = r >> 3;
    float v = W[((size_t)kp * IC + chunk * 32 + icl) * OC + ocb * 32 + oc];
    __nv_bfloat16 h = __float2bfloat16(v);
    __nv_bfloat16 l = __float2bfloat16(v - __bfloat162float(h));
    __nv_bfloat16* br = dst + ((size_t)(chunk * 8 + ocb) * 288 + kp * 32 + oc) * 72;
    br[icl] = h; br[32 + icl] = l;
}

// ---------------- LayerNorm over channel axis -> bf16 hi/lo -----------------
__global__ void ln_kernel(const float* __restrict__ x,
                          const float* __restrict__ gamma,
                          const float* __restrict__ beta) {
    int row  = blockIdx.x * 8 + (threadIdx.x >> 5);
    int lane = threadIdx.x & 31;
    float v = x[(size_t)row * CC + lane];
    float s = v, s2 = v * v;
    #pragma unroll
    for (int o = 16; o; o >>= 1) {
        s  += __shfl_xor_sync(0xffffffffu, s,  o);
        s2 += __shfl_xor_sync(0xffffffffu, s2, o);
    }
    float mu  = s * (1.f / 32.f);
    float var = s2 * (1.f / 32.f) - mu * mu;
    float inv = rsqrtf(var + 1e-3f);
    float xn = (v - mu) * inv * gamma[lane] + beta[lane];
    __nv_bfloat16 hi = __float2bfloat16(xn);
    size_t idx = (size_t)row * CC + lane;
    g_xh[idx] = hi;
    g_xl[idx] = __float2bfloat16(xn - __bfloat162float(hi));
}

// A halo staging (shared by both convs): 18x18 tile, bf16 hi|lo per 144B row
#define STAGE_A(Ah, Al, IC, ch0)                                               \
    for (int i = tid; i < 324 * 8; i += 256) {                                 \
        int sp = i >> 3, r = i & 7;                                            \
        int ry = sp / 18, rx = sp - ry * 18;                                   \
        int gy = ty0 - 1 + ry, gx = tx0 - 1 + rx;                              \
        uint4 v = make_uint4(0u, 0u, 0u, 0u);                                  \
        if (gy >= 0 && gy < HH && gx >= 0 && gx < WW) {                        \
            const __nv_bfloat16* src = (r < 4 ? (Ah) : (Al))                   \
                + ((size_t)gy * WW + gx) * (IC) + (ch0) + ((r & 3) << 3);      \
            v = *(const uint4*)src;                                            \
        }                                                                      \
        *(uint4*)(s_a + sp * 144 + ((r & 3) << 4) + ((r < 4) ? 0 : 64)) = v;   \
    }

// MMA inner body over one staged (A chunk, B oc-group): 9 kp x 2 k16 halves
#define MMA_BODY(ACC)                                                          \
    _Pragma("unroll 1")                                                        \
    for (int kp = 0; kp < 9; kp++) {                                           \
        int ky = (kp >= 6) ? 2 : ((kp >= 3) ? 1 : 0);                          \
        int kx = kp - ky * 3;                                                  \
        _Pragma("unroll")                                                      \
        for (int s = 0; s < 2; s++) {                                          \
            u32 bh[4][2], bl[4][2];                                            \
            _Pragma("unroll")                                                  \
            for (int n = 0; n < 4; n++) {                                      \
                const char* bp = s_b + (kp * 32 + n * 8 + gid) * 144 + s * 32 + tig * 4; \
                bh[n][0] = *(const u32*)bp;        bh[n][1] = *(const u32*)(bp + 16); \
                bl[n][0] = *(const u32*)(bp + 64); bl[n][1] = *(const u32*)(bp + 80); \
            }                                                                  \
            _Pragma("unroll")                                                  \
            for (int t = 0; t < 2; t++) {                                      \
                const char* ap = s_a + ((w + 8 * t + ky) * 18 + gid + kx) * 144 \
                               + s * 32 + tig * 4;                             \
                u32 ah0 = *(const u32*)ap;                                     \
                u32 ah2 = *(const u32*)(ap + 16);                              \
                u32 ah1 = *(const u32*)(ap + 8 * 144);                         \
                u32 ah3 = *(const u32*)(ap + 8 * 144 + 16);                    \
                u32 al0 = *(const u32*)(ap + 64);                              \
                u32 al2 = *(const u32*)(ap + 80);                              \
                u32 al1 = *(const u32*)(ap + 8 * 144 + 64);                    \
                u32 al3 = *(const u32*)(ap + 8 * 144 + 80);                    \
                _Pragma("unroll")                                              \
                for (int n = 0; n < 4; n++) {                                  \
                    MMA_BF16(ACC[t][n], ah0, ah1, ah2, ah3, bh[n][0], bh[n][1]); \
                    MMA_BF16(ACC[t][n], ah0, ah1, ah2, ah3, bl[n][0], bl[n][1]); \
                    MMA_BF16(ACC[t][n], al0, al1, al2, al3, bh[n][0], bh[n][1]); \
                }                                                              \
            }                                                                  \
        }                                                                      \
    }

// ---------------- input conv: zx = conv3x3(xn, Wx) + b ----------------------
// grid (2, 16, 64): block stages A ONCE, loops 4 oc-groups (R16-proven).
__global__ __launch_bounds__(256, 2) void convx_mma(
    const __nv_bfloat16* __restrict__ Ahi, const __nv_bfloat16* __restrict__ Alo,
    const __nv_bfloat16* __restrict__ Wp,
    const float* __restrict__ bias, float* __restrict__ zout)
{
    extern __shared__ __align__(16) unsigned char smraw[];
    char* s_a = (char*)smraw;            // 324*144 = 46656 B
    char* s_b = (char*)smraw + 46656;    // 288*144 = 41472 B

    int ocq = blockIdx.x, tile = blockIdx.y, img = blockIdx.z;
    int tid = threadIdx.x;
    int ty0 = (tile >> 2) * 16, tx0 = (tile & 3) * 16;
    int w = tid >> 5, lane = tid & 31, gid = lane >> 2, tig = lane & 3;

    const __nv_bfloat16* Ah = Ahi + (size_t)img * HH * WW * CC;
    const __nv_bfloat16* Al = Alo + (size_t)img * HH * WW * CC;
    STAGE_A(Ah, Al, CC, 0)

    float* zo = zout + (size_t)img * HH * WW * OC;

    #pragma unroll 1
    for (int ocp = 0; ocp < 4; ocp++) {
        int ocb = ocq * 4 + ocp, oc0 = ocb * 32;
        {
            const uint4* wsrc = (const uint4*)(Wp + (size_t)ocb * 288 * 72);
            uint4* wdst = (uint4*)s_b;
            for (int i = tid; i < 2592; i += 256) wdst[i] = wsrc[i];
        }
        __syncthreads();

        float acc[2][4][4];
        #pragma unroll
        for (int n = 0; n < 4; n++) {
            float b0 = bias[oc0 + n * 8 + tig * 2];
            float b1 = bias[oc0 + n * 8 + tig * 2 + 1];
            #pragma unroll
            for (int t = 0; t < 2; t++) {
                acc[t][n][0] = b0; acc[t][n][1] = b1;
                acc[t][n][2] = b0; acc[t][n][3] = b1;
            }
        }

        MMA_BODY(acc)

        #pragma unroll
        for (int t = 0; t < 2; t++) {
            int y = ty0 + w + t * 8;
            float* r1 = zo + ((size_t)y * WW + tx0 + gid) * OC + oc0 + tig * 2;
            #pragma unroll
            for (int n = 0; n < 4; n++) {
                *(float2*)(r1 + n * 8)          = make_float2(acc[t][n][0], acc[t][n][1]);
                *(float2*)(r1 + 8 * OC + n * 8) = make_float2(acc[t][n][2], acc[t][n][3]);
            }
        }
        __syncthreads();
    }
}

// ---------------- recurrent conv: z = zx[:,t] + conv3x3(h, Wh) --------------
// grid (8, 16, 4): one oc-block per block, 2 ic chunks (R15-proven, 512 blocks).
__global__ __launch_bounds__(256, 2) void convh_mma(
    const __nv_bfloat16* __restrict__ Ahi, const __nv_bfloat16* __restrict__ Alo,
    const __nv_bfloat16* __restrict__ Wp,
    const float* __restrict__ zseed, float* __restrict__ zout, int t_step)
{
    extern __shared__ __align__(16) unsigned char smraw[];
    char* s_a = (char*)smraw;            // 46656 B
    char* s_b = (char*)smraw + 46656;    // 41472 B

    int ocb = blockIdx.x, tile = blockIdx.y, img = blockIdx.z;
    int tid = threadIdx.x;
    int ty0 = (tile >> 2) * 16, tx0 = (tile & 3) * 16;
    int oc0 = ocb * 32;
    int w = tid >> 5, lane = tid & 31, gid = lane >> 2, tig = lane & 3;

    float acc[2][4][4];
    {
        const float* zs = zseed + ((size_t)(img * TT + t_step) * HH * WW) * OC;
        #pragma unroll
        for (int t = 0; t < 2; t++) {
            int y = ty0 + w + t * 8;
            const float* r1 = zs + ((size_t)y * WW + tx0 + gid) * OC + oc0 + tig * 2;
            #pragma unroll
            for (int n = 0; n < 4; n++) {
                float2 v1 = *(const float2*)(r1 + n * 8);
                float2 v2 = *(const float2*)(r1 + 8 * OC + n * 8);
                acc[t][n][0] = v1.x; acc[t][n][1] = v1.y;
                acc[t][n][2] = v2.x; acc[t][n][3] = v2.y;
            }
        }
    }

    const __nv_bfloat16* Ah = Ahi + (size_t)img * HH * WW * FF;
    const __nv_bfloat16* Al = Alo + (size_t)img * HH * WW * FF;

    #pragma unroll 1
    for (int chunk = 0; chunk < 2; chunk++) {
        if (chunk) __syncthreads();
        STAGE_A(Ah, Al, FF, chunk * 32)
        {
            const uint4* wsrc = (const uint4*)(Wp + (size_t)(chunk * 8 + ocb) * 288 * 72);
            uint4* wdst = (uint4*)s_b;
            for (int i = tid; i < 2592; i += 256) wdst[i] = wsrc[i];
        }
        __syncthreads();

        MMA_BODY(acc)
    }

    float* zo = zout + (size_t)img * HH * WW * OC;
    #pragma unroll
    for (int t = 0; t < 2; t++) {
        int y = ty0 + w + t * 8;
        float* r1 = zo + ((size_t)y * WW + tx0 + gid) * OC + oc0 + tig * 2;
        #pragma unroll
        for (int n = 0; n < 4; n++) {
            *(float2*)(r1 + n * 8)          = make_float2(acc[t][n][0], acc[t][n][1]);
            *(float2*)(r1 + 8 * OC + n * 8) = make_float2(acc[t][n][2], acc[t][n][3]);
        }
    }
}

// ---------------- LSTM gates + MaxPool(2x2) fused ---------------------------
// FIRST=true: t=0 path — z comes straight from g_zx (conv(h0)=0), c_prev=0,
// so this kernel also fully initializes g_c / g_hh / g_hl (no zero kernel).
template<bool FIRST>
__global__ void gatepool_kernel(const float* __restrict__ zsrc, size_t bstride,
                                float* __restrict__ out, int t) {
    int i = blockIdx.x * blockDim.x + threadIdx.x;   // B*32*32*F = 262144
    if (i >= BB * 32 * 32 * FF) return;
    int f = i & 63;
    int r = i >> 6;
    int xo = r & 31; r >>= 5;
    int yo = r & 31;
    int b  = r >> 5;

    const float* zb = zsrc + (size_t)b * bstride;
    float m = -1e30f;
    #pragma unroll
    for (int dy = 0; dy < 2; dy++) {
        #pragma unroll
        for (int dx = 0; dx < 2; dx++) {
            int y = yo * 2 + dy, x = xo * 2 + dx;
            const float* z = zb + ((size_t)y * WW + x) * OC;
            float zi = z[f], zf = z[64 + f], zc = z[128 + f], zo_ = z[192 + f];
            float ig = __saturatef(0.2f * zi + 0.5f);
            float og = __saturatef(0.2f * zo_ + 0.5f);
            size_t hi = (((size_t)b * HH + y) * WW + x) * FF + f;
            float c;
            if (FIRST) {
                c = ig * ftanh(zc);
            } else {
                float fg = __saturatef(0.2f * zf + 0.5f);
                c = fg * g_c[hi] + ig * ftanh(zc);
            }
            g_c[hi] = c;
            float h = og * ftanh(c);
            __nv_bfloat16 hh = __float2bfloat16(h);
            g_hh[hi] = hh;
            g_hl[hi] = __float2bfloat16(h - __bfloat162float(hh));
            m = fmaxf(m, h);
        }
    }
    out[(((((size_t)b * TT) + t) * 32 + yo) * 32 + xo) * FF + f] = m;
}

// ---------------- launch ----------------------------------------------------
extern "C" void kernel_launch(void* const* d_in, const int* in_sizes, int n_in,
                              void* d_out, int out_size) {
    const float* x     = (const float*)d_in[0];
    const float* gamma = (const float*)d_in[1];
    const float* beta  = (const float*)d_in[2];
    const float* Wx    = (const float*)d_in[3];
    const float* Wh    = (const float*)d_in[4];
    const float* bias  = (const float*)d_in[5];
    float* out = (float*)d_out;

    const int SMEM = 46656 + 41472;   // 88128 B -> 2 CTAs/SM
    cudaFuncSetAttribute(convx_mma, cudaFuncAttributeMaxDynamicSharedMemorySize, SMEM);
    cudaFuncSetAttribute(convh_mma, cudaFuncAttributeMaxDynamicSharedMemorySize, SMEM);

    __nv_bfloat16 *d_xh, *d_xl, *d_hh, *d_hl, *d_wx, *d_wh;
    float *d_zx, *d_z;
    cudaGetSymbolAddress((void**)&d_xh, g_xh);
    cudaGetSymbolAddress((void**)&d_xl, g_xl);
    cudaGetSymbolAddress((void**)&d_hh, g_hh);
    cudaGetSymbolAddress((void**)&d_hl, g_hl);
    cudaGetSymbolAddress((void**)&d_wx, g_wx);
    cudaGetSymbolAddress((void**)&d_wh, g_wh);
    cudaGetSymbolAddress((void**)&d_zx, g_zx);
    cudaGetSymbolAddress((void**)&d_z,  g_z);

    const int GP_GRID = (BB * 32 * 32 * FF + 255) / 256;

    // pack weights to bf16 hi/lo smem-image layout (every call: deterministic)
    packw_kernel<<<(1*8*9*32*32 + 255) / 256, 256>>>(Wx, d_wx, CC);
    packw_kernel<<<(2*8*9*32*32 + 255) / 256, 256>>>(Wh, d_wh, FF);

    // LayerNorm -> bf16 hi/lo
    ln_kernel<<<(BB * TT * HH * WW) / 8, 256>>>(x, gamma, beta);

    // input conv over all timesteps at once (tensor pipe)
    convx_mma<<<dim3(2, 16, BB * TT), 256, SMEM>>>(d_xh, d_xl, d_wx, bias, d_zx);

    // t = 0: h==0 -> z == zx; gates read g_zx directly, init c/h
    gatepool_kernel<true><<<GP_GRID, 256>>>(
        d_zx, (size_t)TT * HH * WW * OC, out, 0);

    // recurrent loop
    for (int t = 1; t < TT; t++) {
        convh_mma<<<dim3(8, 16, BB), 256, SMEM>>>(d_hh, d_hl, d_wh, d_zx, d_z, t);
        gatepool_kernel<false><<<GP_GRID, 256>>>(
            d_z, (size_t)HH * WW * OC, out, t);
    }
}